// round 13
// baseline (speedup 1.0000x reference)
#include <cuda_runtime.h>
#include <cuda_fp16.h>
#include <cstdint>

#define Bn 64
#define Tn 188
#define In 512
#define Hn 1024
#define G4 (4*Hn)
#define NCTA 144
#define NTHR 256

// ---------------- persistent device scratch (allocation-free rule) ----------
__device__ float  g_prex[(size_t)Tn * Bn * G4];     // [t][b_orig][gate*1024+j]
__device__ float  g_P[(size_t)3 * Bn * 6144];       // [sp*64+col(bp)][row]
__device__ float  g_c[2][Bn * Hn];                  // fp32 cell state (permuted b)
__device__ __half g_ht[2][Bn * Hn];                 // fp16 hidden (permuted b)
__device__ __half g_ct[2][Bn * Hn];                 // fp16 cell (permuted b)
__device__ uint4  g_Wpk[(size_t)NCTA * 6144];       // packed fp16 W frags per CTA
__device__ uint4  g_Wpih[(size_t)32 * 8192];        // packed fp16 Wih frags per m-tile
__device__ __half g_X[(size_t)Bn * Tn * In];        // x fp16
__device__ int    g_perm[Bn];                       // bp -> original b
__device__ int    g_na[Tn];                         // exact active count per step
__device__ volatile unsigned g_flags[NCTA * 8];     // per-CTA epoch flags, 32B stride

__device__ __forceinline__ float sigf(float x){ return 1.f / (1.f + __expf(-x)); }

#define CPA16(dst, src) \
    asm volatile("cp.async.cg.shared.global [%0], [%1], 16;" :: "r"(dst), "l"(src) : "memory")
#define CPC()  asm volatile("cp.async.commit_group;" ::: "memory")
#define CPW(n) asm volatile("cp.async.wait_group %0;" :: "n"(n) : "memory")

#define MMA_F16(acc, a0,a1,a2,a3, b0,b1) \
    asm volatile("mma.sync.aligned.m16n8k16.row.col.f32.f16.f16.f32 " \
        "{%0,%1,%2,%3}, {%4,%5,%6,%7}, {%8,%9}, {%0,%1,%2,%3};" \
        : "+f"((acc)[0]), "+f"((acc)[1]), "+f"((acc)[2]), "+f"((acc)[3]) \
        : "r"(a0), "r"(a1), "r"(a2), "r"(a3), "r"(b0), "r"(b1))

__device__ __forceinline__ uint32_t lds32(uint32_t a){
    uint32_t v; asm volatile("ld.shared.b32 %0, [%1];" : "=r"(v) : "r"(a)); return v;
}
__device__ __forceinline__ uint32_t h2pk(float a, float b){
    __half2 h = __floats2half2_rn(a, b);
    return *(uint32_t*)&h;
}

// balanced K-split: sp0 -> chunks [0,11), sp1 -> [11,22), sp2 -> [22,32)
__device__ __host__ __forceinline__ int sp_ck0(int sp){ return (sp < 2) ? sp * 11 : 22; }
__device__ __host__ __forceinline__ int sp_nch(int sp){ return (sp == 2) ? 10 : 11; }

// ---------------------------------------------------------------------------
// Prep kernels
// ---------------------------------------------------------------------------
__device__ __forceinline__ float Wat(const float* whh, const float* wrec, int r, int c){
    return (r < 4096) ? whh[(size_t)r * Hn + c] : wrec[(size_t)(r - 4096) * Hn + c];
}

// persist W pack (R8 frag scheme): slot=(((ck*2+kk)*4+w)*2+mt)*32+lane
__global__ void pack_w(const float* __restrict__ whh, const float* __restrict__ wrec){
    const int total = NCTA * 6144;
    for (int s = blockIdx.x * blockDim.x + threadIdx.x; s < total;
         s += gridDim.x * blockDim.x){
        int cta = s / 6144, idx = s % 6144;
        int tt = cta / 3, sp = cta % 3;
        int nch = sp_nch(sp);
        int lane = idx & 31; int r = idx >> 5;
        int mt = r & 1; r >>= 1;
        int w  = r & 3; r >>= 2;
        int kk = r & 1; int ck = r >> 1;
        if (ck >= nch) continue;
        int g = lane >> 2, t = lane & 3;
        int R0 = tt * 128 + w * 32 + mt * 16 + g;
        int C0 = (sp_ck0(sp) + ck) * 32 + kk * 16 + 2 * t;
        uint4 v;
        v.x = h2pk(Wat(whh, wrec, R0,     C0),     Wat(whh, wrec, R0,     C0 + 1));
        v.y = h2pk(Wat(whh, wrec, R0 + 8, C0),     Wat(whh, wrec, R0 + 8, C0 + 1));
        v.z = h2pk(Wat(whh, wrec, R0,     C0 + 8), Wat(whh, wrec, R0,     C0 + 9));
        v.w = h2pk(Wat(whh, wrec, R0 + 8, C0 + 8), Wat(whh, wrec, R0 + 8, C0 + 9));
        g_Wpk[(size_t)cta * 6144 + idx] = v;
    }
}

// Wih pack (VALIDATED R9)
__global__ void pack_wih(const float* __restrict__ wih){
    const int total = 32 * 8192;
    for (int s = blockIdx.x * blockDim.x + threadIdx.x; s < total;
         s += gridDim.x * blockDim.x){
        int mtile = s / 8192, idx = s % 8192;
        int lane = idx & 31; int r = idx >> 5;
        int mt = r & 1; r >>= 1;
        int w  = r & 3; r >>= 2;
        int kk = r & 1; int ck = r >> 1;
        int g = lane >> 2, t = lane & 3;
        int R0 = mtile * 128 + w * 32 + mt * 16 + g;
        int C0 = ck * 32 + kk * 16 + 2 * t;
        const float* p0 = wih + (size_t)R0 * In;
        const float* p1 = wih + (size_t)(R0 + 8) * In;
        uint4 v;
        v.x = h2pk(p0[C0],     p0[C0 + 1]);
        v.y = h2pk(p1[C0],     p1[C0 + 1]);
        v.z = h2pk(p0[C0 + 8], p0[C0 + 9]);
        v.w = h2pk(p1[C0 + 8], p1[C0 + 9]);
        g_Wpih[s] = v;
    }
}

__global__ void cvt_x(const float* __restrict__ x){
    const size_t n3 = (size_t)Bn * Tn * In;
    for (size_t i = (size_t)blockIdx.x * blockDim.x + threadIdx.x; i < n3;
         i += (size_t)gridDim.x * blockDim.x)
        g_X[i] = __float2half_rn(x[i]);
}

__global__ void out_zero(float* __restrict__ out, size_t n4){
    float4 z = make_float4(0.f, 0.f, 0.f, 0.f);
    for (size_t i = (size_t)blockIdx.x * blockDim.x + threadIdx.x; i < n4;
         i += (size_t)gridDim.x * blockDim.x)
        ((float4*)out)[i] = z;
}

// rank-sort lengths descending (stable), per-step active counts
__global__ void prep_sort(const int* __restrict__ lengths){
    __shared__ int sl[Bn];
    int tid = threadIdx.x;
    if (tid < Bn) sl[tid] = lengths[tid];
    __syncthreads();
    if (tid < Bn){
        int L = sl[tid]; int r = 0;
#pragma unroll
        for (int k = 0; k < Bn; k++)
            r += (sl[k] > L) || (sl[k] == L && k < tid);
        g_perm[r] = tid;
    }
    if (tid < Tn){
        int c = 0;
#pragma unroll
        for (int k = 0; k < Bn; k++) c += (sl[k] > tid);
        g_na[tid] = c;
    }
}

__global__ void init_state(const float* __restrict__ h0, const float* __restrict__ c0){
    int i = blockIdx.x * blockDim.x + threadIdx.x;
    if (i < NCTA * 8) g_flags[i] = 0;               // reset barrier flags each replay
    if (i < Bn * Hn){
        int bp = i >> 10, j = i & (Hn - 1);
        int b = g_perm[bp];
        float h = h0[(size_t)b * Hn + j], c = c0[(size_t)b * Hn + j];
        g_c[0][i]  = c;
        g_ht[0][i] = __float2half_rn(h);
        g_ct[0][i] = __float2half_rn(c);
    }
}

// ---------------------------------------------------------------------------
// fp16 input-projection GEMM (VALIDATED R9/R10) + dead-tile skip
// ---------------------------------------------------------------------------
#define PXB 5120
#define PX_SMEM (2 * PXB)

__global__ void __launch_bounds__(128)
gemm_prex(const float* __restrict__ bias, const int* __restrict__ lengths)
{
    const int nb = blockIdx.y;
    {
        int n0 = nb * 64;
        int b0 = n0 / Tn, t0 = n0 - b0 * Tn;
        bool cross = ((n0 + 63) / Tn) != b0;
        if (!cross && t0 >= __ldg(&lengths[b0])) return;
    }

    extern __shared__ __align__(16) char smc[];
    const uint32_t sb = (uint32_t)__cvta_generic_to_shared(smc);
    const int tid = threadIdx.x;
    const int wid = tid >> 5;
    const int lane = tid & 31;
    const int g = lane >> 2, t = lane & 3;
    const int m = blockIdx.x;

    const uint4* __restrict__ Ap = g_Wpih + (size_t)m * 8192;
    const __half* __restrict__ B = g_X + (size_t)nb * 64 * In;

    float acc[2][8][4];
#pragma unroll
    for (int mt = 0; mt < 2; mt++)
#pragma unroll
        for (int j = 0; j < 8; j++)
#pragma unroll
            for (int q = 0; q < 4; q++) acc[mt][j][q] = 0.f;

#define PX_ST(buf, ck) do {                                                    \
        for (int u = tid; u < 256; u += 128){                                  \
            int rr = u >> 2, uu = u & 3;                                       \
            CPA16(sb + (buf) * PXB + rr * 80 + uu * 16,                        \
                  B + (size_t)rr * In + (ck) * 32 + uu * 8);                   \
        }                                                                      \
    } while (0)

#define PX_LDA(dst, ck) do {                                                   \
        (dst)[0][0] = Ap[((((ck) * 2 + 0) * 4 + wid) * 2 + 0) * 32 + lane];    \
        (dst)[0][1] = Ap[((((ck) * 2 + 0) * 4 + wid) * 2 + 1) * 32 + lane];    \
        (dst)[1][0] = Ap[((((ck) * 2 + 1) * 4 + wid) * 2 + 0) * 32 + lane];    \
        (dst)[1][1] = Ap[((((ck) * 2 + 1) * 4 + wid) * 2 + 1) * 32 + lane];    \
    } while (0)

    PX_ST(0, 0); CPC();
    uint4 av[2][2];
    PX_LDA(av, 0);

#pragma unroll 1
    for (int ch = 0; ch < 16; ch++){
        CPW(0);
        __syncthreads();
        if (ch + 1 < 16){ PX_ST((ch + 1) & 1, ch + 1); CPC(); }
        uint4 nx[2][2];
        if (ch + 1 < 16) PX_LDA(nx, ch + 1);

        const uint32_t Bb = sb + (ch & 1) * PXB;
#pragma unroll
        for (int kk = 0; kk < 2; kk++){
            uint32_t b[8][2];
#pragma unroll
            for (int j = 0; j < 8; j++){
                uint32_t bbase = Bb + (j * 8 + g) * 80 + kk * 32 + t * 4;
                b[j][0] = lds32(bbase);
                b[j][1] = lds32(bbase + 16);
            }
#pragma unroll
            for (int mt = 0; mt < 2; mt++){
                uint4 a = av[kk][mt];
#pragma unroll
                for (int j = 0; j < 8; j++)
                    MMA_F16(acc[mt][j], a.x, a.y, a.z, a.w, b[j][0], b[j][1]);
            }
        }
        if (ch + 1 < 16){
            av[0][0] = nx[0][0]; av[0][1] = nx[0][1];
            av[1][0] = nx[1][0]; av[1][1] = nx[1][1];
        }
    }

#pragma unroll
    for (int mt = 0; mt < 2; mt++){
        int rowb = m * 128 + wid * 32 + mt * 16;
        float bs0 = bias[rowb + g];
        float bs1 = bias[rowb + g + 8];
#pragma unroll
        for (int j = 0; j < 8; j++)
#pragma unroll
            for (int q = 0; q < 4; q++){
                int row = rowb + g + (q >> 1) * 8;
                int n   = blockIdx.y * 64 + j * 8 + t * 2 + (q & 1);
                int bq  = n / Tn, tq = n - bq * Tn;
                g_prex[((size_t)tq * Bn + bq) * G4 + row] =
                    acc[mt][j][q] + ((q >> 1) ? bs1 : bs0);
            }
    }
}

// ---------------------------------------------------------------------------
// Persistent recurrent kernel: balanced split + vectorized cell phase
// ---------------------------------------------------------------------------
#define SWB  90112                      // 11 chunks * 512 uint4 * 16B
#define BBUF 5120
#define PERS_SMEM (SWB + 11 * BBUF)     // 88KB W + 55KB B = 143KB

__device__ __forceinline__ void gridbar(unsigned ep){
    __syncthreads();
    if (threadIdx.x == 0){
        __threadfence();
        g_flags[blockIdx.x * 8] = ep;
    }
    if (threadIdx.x < NCTA){
        while (g_flags[threadIdx.x * 8] < ep) { }
    }
    __syncthreads();
    __threadfence();
}

__global__ void __launch_bounds__(NTHR, 1)
persist_kernel(float* __restrict__ out, int writeC)
{
    extern __shared__ __align__(16) char smc[];
    const uint32_t sb = (uint32_t)__cvta_generic_to_shared(smc);
    const uint4* sW4 = (const uint4*)smc;
    const int tid  = threadIdx.x;
    const int wid  = tid >> 5;
    const int lane = tid & 31;
    const int g = lane >> 2, t = lane & 3;
    const int w4 = wid & 3;
    const int mt = wid >> 2;
    const int cta  = blockIdx.x;
    const int tt   = cta / 3;
    const int sp   = cta % 3;
    const int spk0 = sp_ck0(sp) * 32;
    const int nch  = sp_nch(sp);

    // one-time load of packed fp16 W tile
    {
        const uint4* src = &g_Wpk[(size_t)cta * 6144];
        int n4 = nch * 512;
        for (int u = tid; u < n4; u += NTHR)
            CPA16(sb + u * 16, (const char*)(src + u));
        CPC(); CPW(0);
        __syncthreads();
    }

    const size_t BTH = (size_t)Bn * Tn * Hn;
    unsigned ep = 0;

#pragma unroll 1
    for (int tstep = 0; tstep < Tn; tstep++){
        const int par = tstep & 1, np = par ^ 1;
        const int na = __ldg(&g_na[tstep]);
        const int nj = (na + 7) >> 3;
        if (nj == 0) break;
        const int ract = nj << 3;
        const __half* __restrict__ Bsrc = (tt < 32) ? g_ht[par] : g_ct[par];

        // ---- single-shot staging of ALL B chunks ----
        {
            int rr = tid >> 2, uu = tid & 3;
            if (rr < ract){
                const __half* rp = Bsrc + (size_t)rr * Hn + spk0;
                uint32_t dst = sb + SWB + rr * 80 + uu * 16;
#pragma unroll 1
                for (int ck = 0; ck < nch; ck++)
                    CPA16(dst + ck * BBUF, rp + ck * 32 + uu * 8);
            }
            CPC(); CPW(0);
            __syncthreads();
        }

        // ---- MMA: all 8 warps, no internal syncs ----
        float acc[8][4];
#pragma unroll
        for (int j = 0; j < 8; j++)
#pragma unroll
            for (int q = 0; q < 4; q++) acc[j][q] = 0.f;

#pragma unroll 1
        for (int ck = 0; ck < nch; ck++){
            const uint32_t Bb = sb + SWB + ck * BBUF;
#pragma unroll
            for (int kk = 0; kk < 2; kk++){
                uint4 av = sW4[((((ck * 2 + kk) * 4 + w4) * 2 + mt) * 32) + lane];
                uint32_t b[8][2];
#pragma unroll
                for (int j = 0; j < 8; j++) if (j < nj){
                    uint32_t bbase = Bb + (j * 8 + g) * 80 + kk * 32 + t * 4;
                    b[j][0] = lds32(bbase);
                    b[j][1] = lds32(bbase + 16);
                }
#pragma unroll
                for (int j = 0; j < 8; j++) if (j < nj)
                    MMA_F16(acc[j], av.x, av.y, av.z, av.w, b[j][0], b[j][1]);
            }
        }

        // epilogue: partials -> g_P[(sp*64+col)][row], active tiles only
#pragma unroll
        for (int j = 0; j < 8; j++) if (j < nj)
#pragma unroll
            for (int q = 0; q < 4; q++){
                int row = tt * 128 + w4 * 32 + mt * 16 + g + (q >> 1) * 8;
                int col = j * 8 + t * 2 + (q & 1);
                g_P[((size_t)(sp * 64 + col)) * 6144 + row] = acc[j][q];
            }

        gridbar(++ep);

        // ---- fused cell phase: 4 j per thread (float4), round-robin quads ----
        const int ncell4 = na << 8;
        for (int q4 = cta + tid * NCTA; q4 < ncell4; q4 += NCTA * NTHR){
            int bp = q4 >> 8;
            int j4 = (q4 & 255) << 2;
            int borig = __ldg(&g_perm[bp]);

            float si[4] = {0,0,0,0}, sf[4] = {0,0,0,0};
            float sg[4] = {0,0,0,0}, so[4] = {0,0,0,0};
#pragma unroll
            for (int s2 = 0; s2 < 3; s2++){
                const float* Pp = g_P + ((size_t)(s2 * 64 + bp)) * 6144 + j4;
                float4 pi4 = *(const float4*)&Pp[0];
                float4 pf4 = *(const float4*)&Pp[1024];
                float4 pg4 = *(const float4*)&Pp[2048];
                float4 po4 = *(const float4*)&Pp[3072];
                float4 ri4 = *(const float4*)&Pp[4096];
                float4 rf4 = *(const float4*)&Pp[5120];
                si[0] += pi4.x + ri4.x; si[1] += pi4.y + ri4.y;
                si[2] += pi4.z + ri4.z; si[3] += pi4.w + ri4.w;
                sf[0] += pf4.x + rf4.x; sf[1] += pf4.y + rf4.y;
                sf[2] += pf4.z + rf4.z; sf[3] += pf4.w + rf4.w;
                sg[0] += pg4.x; sg[1] += pg4.y; sg[2] += pg4.z; sg[3] += pg4.w;
                so[0] += po4.x; so[1] += po4.y; so[2] += po4.z; so[3] += po4.w;
            }
            const float* px = g_prex + ((size_t)tstep * Bn + borig) * G4 + j4;
            float4 xi = *(const float4*)&px[0];
            float4 xf = *(const float4*)&px[1024];
            float4 xg = *(const float4*)&px[2048];
            float4 xo = *(const float4*)&px[3072];
            float4 cold = *(const float4*)&g_c[par][bp * Hn + j4];

            float pi[4] = {xi.x + si[0], xi.y + si[1], xi.z + si[2], xi.w + si[3]};
            float pf[4] = {xf.x + sf[0], xf.y + sf[1], xf.z + sf[2], xf.w + sf[3]};
            float pg[4] = {xg.x + sg[0], xg.y + sg[1], xg.z + sg[2], xg.w + sg[3]};
            float po[4] = {xo.x + so[0], xo.y + so[1], xo.z + so[2], xo.w + so[3]};
            float co[4] = {cold.x, cold.y, cold.z, cold.w};

            float cn[4], hn[4];
#pragma unroll
            for (int u = 0; u < 4; u++){
                float ig = sigf(pi[u]);
                float fg = sigf(pf[u]);
                float gv = tanhf(pg[u]);
                cn[u] = fg * co[u] + ig * gv;
                float og = sigf(po[u] + cn[u]);
                hn[u] = og * tanhf(cn[u]);
            }

            *(float4*)&g_c[np][bp * Hn + j4] = make_float4(cn[0], cn[1], cn[2], cn[3]);
            uint2 hh, cc;
            hh.x = h2pk(hn[0], hn[1]); hh.y = h2pk(hn[2], hn[3]);
            cc.x = h2pk(cn[0], cn[1]); cc.y = h2pk(cn[2], cn[3]);
            *(uint2*)&g_ht[np][bp * Hn + j4] = hh;
            *(uint2*)&g_ct[np][bp * Hn + j4] = cc;

            size_t ob = ((size_t)borig * Tn + tstep) * Hn + j4;
            *(float4*)&out[ob] = make_float4(hn[0], hn[1], hn[2], hn[3]);
            if (writeC)
                *(float4*)&out[BTH + ob] = make_float4(cn[0], cn[1], cn[2], cn[3]);
        }

        gridbar(++ep);
    }
}

// ---------------------------------------------------------------------------
extern "C" void kernel_launch(void* const* d_in, const int* in_sizes, int n_in,
                              void* d_out, int out_size)
{
    const float* x    = (const float*)d_in[0];
    const float* h0   = (const float*)d_in[1];
    const float* c0   = (const float*)d_in[2];
    const float* wih  = (const float*)d_in[3];
    const float* whh  = (const float*)d_in[4];
    const float* wrec = (const float*)d_in[5];
    const float* bias = (const float*)d_in[6];
    const int* lengths = (const int*)d_in[7];
    float* out = (float*)d_out;
    int writeC = (out_size >= 2 * Bn * Tn * Hn) ? 1 : 0;

    cudaFuncSetAttribute(gemm_prex, cudaFuncAttributeMaxDynamicSharedMemorySize, PX_SMEM);
    cudaFuncSetAttribute(persist_kernel, cudaFuncAttributeMaxDynamicSharedMemorySize, PERS_SMEM);

    prep_sort<<<1, 256>>>(lengths);
    pack_w<<<1024, 256>>>(whh, wrec);
    pack_wih<<<512, 256>>>(wih);
    cvt_x<<<1024, 256>>>(x);
    out_zero<<<1024, 256>>>(out, (size_t)out_size / 4);
    init_state<<<256, 256>>>(h0, c0);
    gemm_prex<<<dim3(32, 188), 128, PX_SMEM>>>(bias, lengths);
    persist_kernel<<<NCTA, NTHR, PERS_SMEM>>>(out, writeC);
}

// round 14
// speedup vs baseline: 1.0705x; 1.0705x over previous
#include <cuda_runtime.h>
#include <cuda_fp16.h>
#include <cstdint>

#define Bn 64
#define Tn 188
#define In 512
#define Hn 1024
#define G4 (4*Hn)
#define NCTA 144
#define NTHR 256

// ---------------- persistent device scratch (allocation-free rule) ----------
__device__ float  g_prex[(size_t)Tn * Bn * G4];     // [t][b_orig][gate*1024+j]
__device__ float  g_P[(size_t)3 * Bn * 6144];       // [sp*64+col(bp)][row]
__device__ float  g_c[2][Bn * Hn];                  // fp32 cell state (permuted b)
__device__ __half g_ht[2][Bn * Hn];                 // fp16 hidden (permuted b)
__device__ __half g_ct[2][Bn * Hn];                 // fp16 cell (permuted b)
__device__ uint4  g_Wpk[(size_t)NCTA * 6144];       // packed fp16 W frags per CTA
__device__ uint4  g_Wpih[(size_t)32 * 8192];        // packed fp16 Wih frags per m-tile
__device__ __half g_X[(size_t)Bn * Tn * In];        // x fp16
__device__ int    g_perm[Bn];                       // bp -> original b
__device__ int    g_na[Tn];                         // exact active count per step
__device__ volatile unsigned g_flags[NCTA * 8];     // per-CTA epoch flags, 32B stride

__device__ __forceinline__ float sigf(float x){ return 1.f / (1.f + __expf(-x)); }

#define CPA16(dst, src) \
    asm volatile("cp.async.cg.shared.global [%0], [%1], 16;" :: "r"(dst), "l"(src) : "memory")
#define CPC()  asm volatile("cp.async.commit_group;" ::: "memory")
#define CPW(n) asm volatile("cp.async.wait_group %0;" :: "n"(n) : "memory")

#define MMA_F16(acc, a0,a1,a2,a3, b0,b1) \
    asm volatile("mma.sync.aligned.m16n8k16.row.col.f32.f16.f16.f32 " \
        "{%0,%1,%2,%3}, {%4,%5,%6,%7}, {%8,%9}, {%0,%1,%2,%3};" \
        : "+f"((acc)[0]), "+f"((acc)[1]), "+f"((acc)[2]), "+f"((acc)[3]) \
        : "r"(a0), "r"(a1), "r"(a2), "r"(a3), "r"(b0), "r"(b1))

__device__ __forceinline__ uint32_t lds32(uint32_t a){
    uint32_t v; asm volatile("ld.shared.b32 %0, [%1];" : "=r"(v) : "r"(a)); return v;
}
__device__ __forceinline__ uint32_t h2pk(float a, float b){
    __half2 h = __floats2half2_rn(a, b);
    return *(uint32_t*)&h;
}

// balanced K-split: sp0 -> chunks [0,11), sp1 -> [11,22), sp2 -> [22,32)
__device__ __host__ __forceinline__ int sp_ck0(int sp){ return (sp < 2) ? sp * 11 : 22; }
__device__ __host__ __forceinline__ int sp_nch(int sp){ return (sp == 2) ? 10 : 11; }

// ---------------------------------------------------------------------------
// Prep kernels
// ---------------------------------------------------------------------------
__device__ __forceinline__ float Wat(const float* whh, const float* wrec, int r, int c){
    return (r < 4096) ? whh[(size_t)r * Hn + c] : wrec[(size_t)(r - 4096) * Hn + c];
}

// persist W pack (R8 frag scheme): slot=(((ck*2+kk)*4+w)*2+mt)*32+lane
__global__ void pack_w(const float* __restrict__ whh, const float* __restrict__ wrec){
    const int total = NCTA * 6144;
    for (int s = blockIdx.x * blockDim.x + threadIdx.x; s < total;
         s += gridDim.x * blockDim.x){
        int cta = s / 6144, idx = s % 6144;
        int tt = cta / 3, sp = cta % 3;
        int nch = sp_nch(sp);
        int lane = idx & 31; int r = idx >> 5;
        int mt = r & 1; r >>= 1;
        int w  = r & 3; r >>= 2;
        int kk = r & 1; int ck = r >> 1;
        if (ck >= nch) continue;
        int g = lane >> 2, t = lane & 3;
        int R0 = tt * 128 + w * 32 + mt * 16 + g;
        int C0 = (sp_ck0(sp) + ck) * 32 + kk * 16 + 2 * t;
        uint4 v;
        v.x = h2pk(Wat(whh, wrec, R0,     C0),     Wat(whh, wrec, R0,     C0 + 1));
        v.y = h2pk(Wat(whh, wrec, R0 + 8, C0),     Wat(whh, wrec, R0 + 8, C0 + 1));
        v.z = h2pk(Wat(whh, wrec, R0,     C0 + 8), Wat(whh, wrec, R0,     C0 + 9));
        v.w = h2pk(Wat(whh, wrec, R0 + 8, C0 + 8), Wat(whh, wrec, R0 + 8, C0 + 9));
        g_Wpk[(size_t)cta * 6144 + idx] = v;
    }
}

// Wih pack (VALIDATED R9)
__global__ void pack_wih(const float* __restrict__ wih){
    const int total = 32 * 8192;
    for (int s = blockIdx.x * blockDim.x + threadIdx.x; s < total;
         s += gridDim.x * blockDim.x){
        int mtile = s / 8192, idx = s % 8192;
        int lane = idx & 31; int r = idx >> 5;
        int mt = r & 1; r >>= 1;
        int w  = r & 3; r >>= 2;
        int kk = r & 1; int ck = r >> 1;
        int g = lane >> 2, t = lane & 3;
        int R0 = mtile * 128 + w * 32 + mt * 16 + g;
        int C0 = ck * 32 + kk * 16 + 2 * t;
        const float* p0 = wih + (size_t)R0 * In;
        const float* p1 = wih + (size_t)(R0 + 8) * In;
        uint4 v;
        v.x = h2pk(p0[C0],     p0[C0 + 1]);
        v.y = h2pk(p1[C0],     p1[C0 + 1]);
        v.z = h2pk(p0[C0 + 8], p0[C0 + 9]);
        v.w = h2pk(p1[C0 + 8], p1[C0 + 9]);
        g_Wpih[s] = v;
    }
}

__global__ void cvt_x(const float* __restrict__ x){
    const size_t n3 = (size_t)Bn * Tn * In;
    for (size_t i = (size_t)blockIdx.x * blockDim.x + threadIdx.x; i < n3;
         i += (size_t)gridDim.x * blockDim.x)
        g_X[i] = __float2half_rn(x[i]);
}

__global__ void out_zero(float* __restrict__ out, size_t n4){
    float4 z = make_float4(0.f, 0.f, 0.f, 0.f);
    for (size_t i = (size_t)blockIdx.x * blockDim.x + threadIdx.x; i < n4;
         i += (size_t)gridDim.x * blockDim.x)
        ((float4*)out)[i] = z;
}

// rank-sort lengths descending (stable), per-step active counts
__global__ void prep_sort(const int* __restrict__ lengths){
    __shared__ int sl[Bn];
    int tid = threadIdx.x;
    if (tid < Bn) sl[tid] = lengths[tid];
    __syncthreads();
    if (tid < Bn){
        int L = sl[tid]; int r = 0;
#pragma unroll
        for (int k = 0; k < Bn; k++)
            r += (sl[k] > L) || (sl[k] == L && k < tid);
        g_perm[r] = tid;
    }
    if (tid < Tn){
        int c = 0;
#pragma unroll
        for (int k = 0; k < Bn; k++) c += (sl[k] > tid);
        g_na[tid] = c;
    }
}

__global__ void init_state(const float* __restrict__ h0, const float* __restrict__ c0){
    int i = blockIdx.x * blockDim.x + threadIdx.x;
    if (i < NCTA * 8) g_flags[i] = 0;               // reset barrier flags each replay
    if (i < Bn * Hn){
        int bp = i >> 10, j = i & (Hn - 1);
        int b = g_perm[bp];
        float h = h0[(size_t)b * Hn + j], c = c0[(size_t)b * Hn + j];
        g_c[0][i]  = c;
        g_ht[0][i] = __float2half_rn(h);
        g_ct[0][i] = __float2half_rn(c);
    }
}

// ---------------------------------------------------------------------------
// fp16 input-projection GEMM (VALIDATED R9/R10) + dead-tile skip
// ---------------------------------------------------------------------------
#define PXB 5120
#define PX_SMEM (2 * PXB)

__global__ void __launch_bounds__(128)
gemm_prex(const float* __restrict__ bias, const int* __restrict__ lengths)
{
    const int nb = blockIdx.y;
    {
        int n0 = nb * 64;
        int b0 = n0 / Tn, t0 = n0 - b0 * Tn;
        bool cross = ((n0 + 63) / Tn) != b0;
        if (!cross && t0 >= __ldg(&lengths[b0])) return;
    }

    extern __shared__ __align__(16) char smc[];
    const uint32_t sb = (uint32_t)__cvta_generic_to_shared(smc);
    const int tid = threadIdx.x;
    const int wid = tid >> 5;
    const int lane = tid & 31;
    const int g = lane >> 2, t = lane & 3;
    const int m = blockIdx.x;

    const uint4* __restrict__ Ap = g_Wpih + (size_t)m * 8192;
    const __half* __restrict__ B = g_X + (size_t)nb * 64 * In;

    float acc[2][8][4];
#pragma unroll
    for (int mt = 0; mt < 2; mt++)
#pragma unroll
        for (int j = 0; j < 8; j++)
#pragma unroll
            for (int q = 0; q < 4; q++) acc[mt][j][q] = 0.f;

#define PX_ST(buf, ck) do {                                                    \
        for (int u = tid; u < 256; u += 128){                                  \
            int rr = u >> 2, uu = u & 3;                                       \
            CPA16(sb + (buf) * PXB + rr * 80 + uu * 16,                        \
                  B + (size_t)rr * In + (ck) * 32 + uu * 8);                   \
        }                                                                      \
    } while (0)

#define PX_LDA(dst, ck) do {                                                   \
        (dst)[0][0] = Ap[((((ck) * 2 + 0) * 4 + wid) * 2 + 0) * 32 + lane];    \
        (dst)[0][1] = Ap[((((ck) * 2 + 0) * 4 + wid) * 2 + 1) * 32 + lane];    \
        (dst)[1][0] = Ap[((((ck) * 2 + 1) * 4 + wid) * 2 + 0) * 32 + lane];    \
        (dst)[1][1] = Ap[((((ck) * 2 + 1) * 4 + wid) * 2 + 1) * 32 + lane];    \
    } while (0)

    PX_ST(0, 0); CPC();
    uint4 av[2][2];
    PX_LDA(av, 0);

#pragma unroll 1
    for (int ch = 0; ch < 16; ch++){
        CPW(0);
        __syncthreads();
        if (ch + 1 < 16){ PX_ST((ch + 1) & 1, ch + 1); CPC(); }
        uint4 nx[2][2];
        if (ch + 1 < 16) PX_LDA(nx, ch + 1);

        const uint32_t Bb = sb + (ch & 1) * PXB;
#pragma unroll
        for (int kk = 0; kk < 2; kk++){
            uint32_t b[8][2];
#pragma unroll
            for (int j = 0; j < 8; j++){
                uint32_t bbase = Bb + (j * 8 + g) * 80 + kk * 32 + t * 4;
                b[j][0] = lds32(bbase);
                b[j][1] = lds32(bbase + 16);
            }
#pragma unroll
            for (int mt = 0; mt < 2; mt++){
                uint4 a = av[kk][mt];
#pragma unroll
                for (int j = 0; j < 8; j++)
                    MMA_F16(acc[mt][j], a.x, a.y, a.z, a.w, b[j][0], b[j][1]);
            }
        }
        if (ch + 1 < 16){
            av[0][0] = nx[0][0]; av[0][1] = nx[0][1];
            av[1][0] = nx[1][0]; av[1][1] = nx[1][1];
        }
    }

#pragma unroll
    for (int mt = 0; mt < 2; mt++){
        int rowb = m * 128 + wid * 32 + mt * 16;
        float bs0 = bias[rowb + g];
        float bs1 = bias[rowb + g + 8];
#pragma unroll
        for (int j = 0; j < 8; j++)
#pragma unroll
            for (int q = 0; q < 4; q++){
                int row = rowb + g + (q >> 1) * 8;
                int n   = blockIdx.y * 64 + j * 8 + t * 2 + (q & 1);
                int bq  = n / Tn, tq = n - bq * Tn;
                g_prex[((size_t)tq * Bn + bq) * G4 + row] =
                    acc[mt][j][q] + ((q >> 1) ? bs1 : bs0);
            }
    }
}

// ---------------------------------------------------------------------------
// Persistent recurrent kernel: balanced split + coalesced vectorized cell
// ---------------------------------------------------------------------------
#define SWB  90112                      // 11 chunks * 512 uint4 * 16B
#define BBUF 5120
#define PERS_SMEM (SWB + 11 * BBUF)     // 88KB W + 55KB B = 143KB

__device__ __forceinline__ void gridbar(unsigned ep){
    __syncthreads();
    if (threadIdx.x == 0){
        __threadfence();
        g_flags[blockIdx.x * 8] = ep;
    }
    if (threadIdx.x < NCTA){
        while (g_flags[threadIdx.x * 8] < ep) { }
    }
    __syncthreads();
    __threadfence();
}

__global__ void __launch_bounds__(NTHR, 1)
persist_kernel(float* __restrict__ out, int writeC)
{
    extern __shared__ __align__(16) char smc[];
    const uint32_t sb = (uint32_t)__cvta_generic_to_shared(smc);
    const uint4* sW4 = (const uint4*)smc;
    const int tid  = threadIdx.x;
    const int wid  = tid >> 5;
    const int lane = tid & 31;
    const int g = lane >> 2, t = lane & 3;
    const int w4 = wid & 3;
    const int mt = wid >> 2;
    const int cta  = blockIdx.x;
    const int tt   = cta / 3;
    const int sp   = cta % 3;
    const int spk0 = sp_ck0(sp) * 32;
    const int nch  = sp_nch(sp);

    // one-time load of packed fp16 W tile
    {
        const uint4* src = &g_Wpk[(size_t)cta * 6144];
        int n4 = nch * 512;
        for (int u = tid; u < n4; u += NTHR)
            CPA16(sb + u * 16, (const char*)(src + u));
        CPC(); CPW(0);
        __syncthreads();
    }

    const size_t BTH = (size_t)Bn * Tn * Hn;
    unsigned ep = 0;

#pragma unroll 1
    for (int tstep = 0; tstep < Tn; tstep++){
        const int par = tstep & 1, np = par ^ 1;
        const int na = __ldg(&g_na[tstep]);
        const int nj = (na + 7) >> 3;
        if (nj == 0) break;
        const int ract = nj << 3;
        const __half* __restrict__ Bsrc = (tt < 32) ? g_ht[par] : g_ct[par];

        // ---- single-shot staging of ALL B chunks ----
        {
            int rr = tid >> 2, uu = tid & 3;
            if (rr < ract){
                const __half* rp = Bsrc + (size_t)rr * Hn + spk0;
                uint32_t dst = sb + SWB + rr * 80 + uu * 16;
#pragma unroll 1
                for (int ck = 0; ck < nch; ck++)
                    CPA16(dst + ck * BBUF, rp + ck * 32 + uu * 8);
            }
            CPC(); CPW(0);
            __syncthreads();
        }

        // ---- MMA: all 8 warps, no internal syncs ----
        float acc[8][4];
#pragma unroll
        for (int j = 0; j < 8; j++)
#pragma unroll
            for (int q = 0; q < 4; q++) acc[j][q] = 0.f;

#pragma unroll 1
        for (int ck = 0; ck < nch; ck++){
            const uint32_t Bb = sb + SWB + ck * BBUF;
#pragma unroll
            for (int kk = 0; kk < 2; kk++){
                uint4 av = sW4[((((ck * 2 + kk) * 4 + w4) * 2 + mt) * 32) + lane];
                uint32_t b[8][2];
#pragma unroll
                for (int j = 0; j < 8; j++) if (j < nj){
                    uint32_t bbase = Bb + (j * 8 + g) * 80 + kk * 32 + t * 4;
                    b[j][0] = lds32(bbase);
                    b[j][1] = lds32(bbase + 16);
                }
#pragma unroll
                for (int j = 0; j < 8; j++) if (j < nj)
                    MMA_F16(acc[j], av.x, av.y, av.z, av.w, b[j][0], b[j][1]);
            }
        }

        // epilogue: partials -> g_P[(sp*64+col)][row], active tiles only
#pragma unroll
        for (int j = 0; j < 8; j++) if (j < nj)
#pragma unroll
            for (int q = 0; q < 4; q++){
                int row = tt * 128 + w4 * 32 + mt * 16 + g + (q >> 1) * 8;
                int col = j * 8 + t * 2 + (q & 1);
                g_P[((size_t)(sp * 64 + col)) * 6144 + row] = acc[j][q];
            }

        gridbar(++ep);

        // ---- fused cell phase: 4 j per thread (float4), CONTIGUOUS quads ----
        const int ncell4 = na << 8;
        for (int q4 = cta * NTHR + tid; q4 < ncell4; q4 += NCTA * NTHR){
            int bp = q4 >> 8;
            int j4 = (q4 & 255) << 2;
            int borig = __ldg(&g_perm[bp]);

            float si[4] = {0,0,0,0}, sf[4] = {0,0,0,0};
            float sg[4] = {0,0,0,0}, so[4] = {0,0,0,0};
#pragma unroll
            for (int s2 = 0; s2 < 3; s2++){
                const float* Pp = g_P + ((size_t)(s2 * 64 + bp)) * 6144 + j4;
                float4 pi4 = *(const float4*)&Pp[0];
                float4 pf4 = *(const float4*)&Pp[1024];
                float4 pg4 = *(const float4*)&Pp[2048];
                float4 po4 = *(const float4*)&Pp[3072];
                float4 ri4 = *(const float4*)&Pp[4096];
                float4 rf4 = *(const float4*)&Pp[5120];
                si[0] += pi4.x + ri4.x; si[1] += pi4.y + ri4.y;
                si[2] += pi4.z + ri4.z; si[3] += pi4.w + ri4.w;
                sf[0] += pf4.x + rf4.x; sf[1] += pf4.y + rf4.y;
                sf[2] += pf4.z + rf4.z; sf[3] += pf4.w + rf4.w;
                sg[0] += pg4.x; sg[1] += pg4.y; sg[2] += pg4.z; sg[3] += pg4.w;
                so[0] += po4.x; so[1] += po4.y; so[2] += po4.z; so[3] += po4.w;
            }
            const float* px = g_prex + ((size_t)tstep * Bn + borig) * G4 + j4;
            float4 xi = *(const float4*)&px[0];
            float4 xf = *(const float4*)&px[1024];
            float4 xg = *(const float4*)&px[2048];
            float4 xo = *(const float4*)&px[3072];
            float4 cold = *(const float4*)&g_c[par][bp * Hn + j4];

            float pi[4] = {xi.x + si[0], xi.y + si[1], xi.z + si[2], xi.w + si[3]};
            float pf[4] = {xf.x + sf[0], xf.y + sf[1], xf.z + sf[2], xf.w + sf[3]};
            float pg[4] = {xg.x + sg[0], xg.y + sg[1], xg.z + sg[2], xg.w + sg[3]};
            float po[4] = {xo.x + so[0], xo.y + so[1], xo.z + so[2], xo.w + so[3]};
            float co[4] = {cold.x, cold.y, cold.z, cold.w};

            float cn[4], hn[4];
#pragma unroll
            for (int u = 0; u < 4; u++){
                float ig = sigf(pi[u]);
                float fg = sigf(pf[u]);
                float gv = tanhf(pg[u]);
                cn[u] = fg * co[u] + ig * gv;
                float og = sigf(po[u] + cn[u]);
                hn[u] = og * tanhf(cn[u]);
            }

            *(float4*)&g_c[np][bp * Hn + j4] = make_float4(cn[0], cn[1], cn[2], cn[3]);
            uint2 hh, cc;
            hh.x = h2pk(hn[0], hn[1]); hh.y = h2pk(hn[2], hn[3]);
            cc.x = h2pk(cn[0], cn[1]); cc.y = h2pk(cn[2], cn[3]);
            *(uint2*)&g_ht[np][bp * Hn + j4] = hh;
            *(uint2*)&g_ct[np][bp * Hn + j4] = cc;

            size_t ob = ((size_t)borig * Tn + tstep) * Hn + j4;
            *(float4*)&out[ob] = make_float4(hn[0], hn[1], hn[2], hn[3]);
            if (writeC)
                *(float4*)&out[BTH + ob] = make_float4(cn[0], cn[1], cn[2], cn[3]);
        }

        gridbar(++ep);
    }
}

// ---------------------------------------------------------------------------
extern "C" void kernel_launch(void* const* d_in, const int* in_sizes, int n_in,
                              void* d_out, int out_size)
{
    const float* x    = (const float*)d_in[0];
    const float* h0   = (const float*)d_in[1];
    const float* c0   = (const float*)d_in[2];
    const float* wih  = (const float*)d_in[3];
    const float* whh  = (const float*)d_in[4];
    const float* wrec = (const float*)d_in[5];
    const float* bias = (const float*)d_in[6];
    const int* lengths = (const int*)d_in[7];
    float* out = (float*)d_out;
    int writeC = (out_size >= 2 * Bn * Tn * Hn) ? 1 : 0;

    cudaFuncSetAttribute(gemm_prex, cudaFuncAttributeMaxDynamicSharedMemorySize, PX_SMEM);
    cudaFuncSetAttribute(persist_kernel, cudaFuncAttributeMaxDynamicSharedMemorySize, PERS_SMEM);

    prep_sort<<<1, 256>>>(lengths);
    pack_w<<<1024, 256>>>(whh, wrec);
    pack_wih<<<512, 256>>>(wih);
    cvt_x<<<1024, 256>>>(x);
    out_zero<<<1024, 256>>>(out, (size_t)out_size / 4);
    init_state<<<256, 256>>>(h0, c0);
    gemm_prex<<<dim3(32, 188), 128, PX_SMEM>>>(bias, lengths);
    persist_kernel<<<NCTA, NTHR, PERS_SMEM>>>(out, writeC);
}

// round 15
// speedup vs baseline: 1.1360x; 1.0611x over previous
#include <cuda_runtime.h>
#include <cuda_fp16.h>
#include <cstdint>

#define Bn 64
#define Tn 188
#define In 512
#define Hn 1024
#define G4 (4*Hn)
#define NCTA 144
#define NTHR 256
#define PTHR 512

// ---------------- persistent device scratch (allocation-free rule) ----------
__device__ float  g_prex[(size_t)Tn * Bn * G4];     // [t][b_orig][gate*1024+j]
__device__ float  g_P[(size_t)3 * Bn * 6144];       // [sp*64+col(bp)][row]
__device__ float  g_c[2][Bn * Hn];                  // fp32 cell state (permuted b)
__device__ __half g_ht[2][Bn * Hn];                 // fp16 hidden (permuted b)
__device__ __half g_ct[2][Bn * Hn];                 // fp16 cell (permuted b)
__device__ uint4  g_Wpk[(size_t)NCTA * 6144];       // packed fp16 W frags per CTA
__device__ uint4  g_Wpih[(size_t)32 * 8192];        // packed fp16 Wih frags per m-tile
__device__ __half g_X[(size_t)Bn * Tn * In];        // x fp16
__device__ int    g_perm[Bn];                       // bp -> original b
__device__ int    g_na[Tn];                         // exact active count per step
__device__ volatile unsigned g_flags[NCTA * 8];     // per-CTA epoch flags, 32B stride

__device__ __forceinline__ float sigf(float x){ return 1.f / (1.f + __expf(-x)); }

#define CPA16(dst, src) \
    asm volatile("cp.async.cg.shared.global [%0], [%1], 16;" :: "r"(dst), "l"(src) : "memory")
#define CPC()  asm volatile("cp.async.commit_group;" ::: "memory")
#define CPW(n) asm volatile("cp.async.wait_group %0;" :: "n"(n) : "memory")

#define MMA_F16(acc, a0,a1,a2,a3, b0,b1) \
    asm volatile("mma.sync.aligned.m16n8k16.row.col.f32.f16.f16.f32 " \
        "{%0,%1,%2,%3}, {%4,%5,%6,%7}, {%8,%9}, {%0,%1,%2,%3};" \
        : "+f"((acc)[0]), "+f"((acc)[1]), "+f"((acc)[2]), "+f"((acc)[3]) \
        : "r"(a0), "r"(a1), "r"(a2), "r"(a3), "r"(b0), "r"(b1))

__device__ __forceinline__ uint32_t lds32(uint32_t a){
    uint32_t v; asm volatile("ld.shared.b32 %0, [%1];" : "=r"(v) : "r"(a)); return v;
}
__device__ __forceinline__ uint32_t h2pk(float a, float b){
    __half2 h = __floats2half2_rn(a, b);
    return *(uint32_t*)&h;
}

// ---------------------------------------------------------------------------
// Prep kernels
// ---------------------------------------------------------------------------
__device__ __forceinline__ float Wat(const float* whh, const float* wrec, int r, int c){
    return (r < 4096) ? whh[(size_t)r * Hn + c] : wrec[(size_t)(r - 4096) * Hn + c];
}

// persist W pack (VALIDATED R8): slot=(((ck*2+kk)*4+w)*2+mt)*32+lane
__global__ void pack_w(const float* __restrict__ whh, const float* __restrict__ wrec){
    const int total = NCTA * 6144;
    for (int s = blockIdx.x * blockDim.x + threadIdx.x; s < total;
         s += gridDim.x * blockDim.x){
        int cta = s / 6144, idx = s % 6144;
        int tt = cta / 3, sp = cta % 3;
        int nch = (sp == 2) ? 8 : 12;
        int lane = idx & 31; int r = idx >> 5;
        int mt = r & 1; r >>= 1;
        int w  = r & 3; r >>= 2;
        int kk = r & 1; int ck = r >> 1;
        if (ck >= nch) continue;
        int g = lane >> 2, t = lane & 3;
        int R0 = tt * 128 + w * 32 + mt * 16 + g;
        int C0 = sp * 384 + ck * 32 + kk * 16 + 2 * t;
        uint4 v;
        v.x = h2pk(Wat(whh, wrec, R0,     C0),     Wat(whh, wrec, R0,     C0 + 1));
        v.y = h2pk(Wat(whh, wrec, R0 + 8, C0),     Wat(whh, wrec, R0 + 8, C0 + 1));
        v.z = h2pk(Wat(whh, wrec, R0,     C0 + 8), Wat(whh, wrec, R0,     C0 + 9));
        v.w = h2pk(Wat(whh, wrec, R0 + 8, C0 + 8), Wat(whh, wrec, R0 + 8, C0 + 9));
        g_Wpk[(size_t)cta * 6144 + idx] = v;
    }
}

// Wih pack (VALIDATED R9)
__global__ void pack_wih(const float* __restrict__ wih){
    const int total = 32 * 8192;
    for (int s = blockIdx.x * blockDim.x + threadIdx.x; s < total;
         s += gridDim.x * blockDim.x){
        int mtile = s / 8192, idx = s % 8192;
        int lane = idx & 31; int r = idx >> 5;
        int mt = r & 1; r >>= 1;
        int w  = r & 3; r >>= 2;
        int kk = r & 1; int ck = r >> 1;
        int g = lane >> 2, t = lane & 3;
        int R0 = mtile * 128 + w * 32 + mt * 16 + g;
        int C0 = ck * 32 + kk * 16 + 2 * t;
        const float* p0 = wih + (size_t)R0 * In;
        const float* p1 = wih + (size_t)(R0 + 8) * In;
        uint4 v;
        v.x = h2pk(p0[C0],     p0[C0 + 1]);
        v.y = h2pk(p1[C0],     p1[C0 + 1]);
        v.z = h2pk(p0[C0 + 8], p0[C0 + 9]);
        v.w = h2pk(p1[C0 + 8], p1[C0 + 9]);
        g_Wpih[s] = v;
    }
}

__global__ void cvt_x(const float* __restrict__ x){
    const size_t n3 = (size_t)Bn * Tn * In;
    for (size_t i = (size_t)blockIdx.x * blockDim.x + threadIdx.x; i < n3;
         i += (size_t)gridDim.x * blockDim.x)
        g_X[i] = __float2half_rn(x[i]);
}

__global__ void out_zero(float* __restrict__ out, size_t n4){
    float4 z = make_float4(0.f, 0.f, 0.f, 0.f);
    for (size_t i = (size_t)blockIdx.x * blockDim.x + threadIdx.x; i < n4;
         i += (size_t)gridDim.x * blockDim.x)
        ((float4*)out)[i] = z;
}

// rank-sort lengths descending (stable), per-step active counts
__global__ void prep_sort(const int* __restrict__ lengths){
    __shared__ int sl[Bn];
    int tid = threadIdx.x;
    if (tid < Bn) sl[tid] = lengths[tid];
    __syncthreads();
    if (tid < Bn){
        int L = sl[tid]; int r = 0;
#pragma unroll
        for (int k = 0; k < Bn; k++)
            r += (sl[k] > L) || (sl[k] == L && k < tid);
        g_perm[r] = tid;
    }
    if (tid < Tn){
        int c = 0;
#pragma unroll
        for (int k = 0; k < Bn; k++) c += (sl[k] > tid);
        g_na[tid] = c;
    }
}

__global__ void init_state(const float* __restrict__ h0, const float* __restrict__ c0){
    int i = blockIdx.x * blockDim.x + threadIdx.x;
    if (i < NCTA * 8) g_flags[i] = 0;               // reset barrier flags each replay
    if (i < Bn * Hn){
        int bp = i >> 10, j = i & (Hn - 1);
        int b = g_perm[bp];
        float h = h0[(size_t)b * Hn + j], c = c0[(size_t)b * Hn + j];
        g_c[0][i]  = c;
        g_ht[0][i] = __float2half_rn(h);
        g_ct[0][i] = __float2half_rn(c);
    }
}

// ---------------------------------------------------------------------------
// fp16 input-projection GEMM (VALIDATED R9/R10) + dead-tile skip
// ---------------------------------------------------------------------------
#define PXB 5120
#define PX_SMEM (2 * PXB)

__global__ void __launch_bounds__(128)
gemm_prex(const float* __restrict__ bias, const int* __restrict__ lengths)
{
    const int nb = blockIdx.y;
    {
        int n0 = nb * 64;
        int b0 = n0 / Tn, t0 = n0 - b0 * Tn;
        bool cross = ((n0 + 63) / Tn) != b0;
        if (!cross && t0 >= __ldg(&lengths[b0])) return;
    }

    extern __shared__ __align__(16) char smc[];
    const uint32_t sb = (uint32_t)__cvta_generic_to_shared(smc);
    const int tid = threadIdx.x;
    const int wid = tid >> 5;
    const int lane = tid & 31;
    const int g = lane >> 2, t = lane & 3;
    const int m = blockIdx.x;

    const uint4* __restrict__ Ap = g_Wpih + (size_t)m * 8192;
    const __half* __restrict__ B = g_X + (size_t)nb * 64 * In;

    float acc[2][8][4];
#pragma unroll
    for (int mt = 0; mt < 2; mt++)
#pragma unroll
        for (int j = 0; j < 8; j++)
#pragma unroll
            for (int q = 0; q < 4; q++) acc[mt][j][q] = 0.f;

#define PX_ST(buf, ck) do {                                                    \
        for (int u = tid; u < 256; u += 128){                                  \
            int rr = u >> 2, uu = u & 3;                                       \
            CPA16(sb + (buf) * PXB + rr * 80 + uu * 16,                        \
                  B + (size_t)rr * In + (ck) * 32 + uu * 8);                   \
        }                                                                      \
    } while (0)

#define PX_LDA(dst, ck) do {                                                   \
        (dst)[0][0] = Ap[((((ck) * 2 + 0) * 4 + wid) * 2 + 0) * 32 + lane];    \
        (dst)[0][1] = Ap[((((ck) * 2 + 0) * 4 + wid) * 2 + 1) * 32 + lane];    \
        (dst)[1][0] = Ap[((((ck) * 2 + 1) * 4 + wid) * 2 + 0) * 32 + lane];    \
        (dst)[1][1] = Ap[((((ck) * 2 + 1) * 4 + wid) * 2 + 1) * 32 + lane];    \
    } while (0)

    PX_ST(0, 0); CPC();
    uint4 av[2][2];
    PX_LDA(av, 0);

#pragma unroll 1
    for (int ch = 0; ch < 16; ch++){
        CPW(0);
        __syncthreads();
        if (ch + 1 < 16){ PX_ST((ch + 1) & 1, ch + 1); CPC(); }
        uint4 nx[2][2];
        if (ch + 1 < 16) PX_LDA(nx, ch + 1);

        const uint32_t Bb = sb + (ch & 1) * PXB;
#pragma unroll
        for (int kk = 0; kk < 2; kk++){
            uint32_t b[8][2];
#pragma unroll
            for (int j = 0; j < 8; j++){
                uint32_t bbase = Bb + (j * 8 + g) * 80 + kk * 32 + t * 4;
                b[j][0] = lds32(bbase);
                b[j][1] = lds32(bbase + 16);
            }
#pragma unroll
            for (int mt = 0; mt < 2; mt++){
                uint4 a = av[kk][mt];
#pragma unroll
                for (int j = 0; j < 8; j++)
                    MMA_F16(acc[mt][j], a.x, a.y, a.z, a.w, b[j][0], b[j][1]);
            }
        }
        if (ch + 1 < 16){
            av[0][0] = nx[0][0]; av[0][1] = nx[0][1];
            av[1][0] = nx[1][0]; av[1][1] = nx[1][1];
        }
    }

#pragma unroll
    for (int mt = 0; mt < 2; mt++){
        int rowb = m * 128 + wid * 32 + mt * 16;
        float bs0 = bias[rowb + g];
        float bs1 = bias[rowb + g + 8];
#pragma unroll
        for (int j = 0; j < 8; j++)
#pragma unroll
            for (int q = 0; q < 4; q++){
                int row = rowb + g + (q >> 1) * 8;
                int n   = blockIdx.y * 64 + j * 8 + t * 2 + (q & 1);
                int bq  = n / Tn, tq = n - bq * Tn;
                g_prex[((size_t)tq * Bn + bq) * G4 + row] =
                    acc[mt][j][q] + ((q >> 1) ? bs1 : bs0);
            }
    }
}

// ---------------------------------------------------------------------------
// Persistent recurrent kernel: R12 structure, 512 threads / 16 warps
//   warp wid: m16 tile = wid&7, n-half jh = wid>>3 (j in [jh*4, jh*4+4))
// ---------------------------------------------------------------------------
#define SWB  98304
#define BBUF 5120
#define PERS_SMEM (SWB + 12 * BBUF)     // 96KB W + 60KB B = 156KB

__device__ __forceinline__ void gridbar(unsigned ep){
    __syncthreads();
    if (threadIdx.x == 0){
        __threadfence();
        g_flags[blockIdx.x * 8] = ep;
    }
    if (threadIdx.x < NCTA){
        while (g_flags[threadIdx.x * 8] < ep) { }
    }
    __syncthreads();
    __threadfence();
}

__global__ void __launch_bounds__(PTHR, 1)
persist_kernel(float* __restrict__ out, int writeC)
{
    extern __shared__ __align__(16) char smc[];
    const uint32_t sb = (uint32_t)__cvta_generic_to_shared(smc);
    const uint4* sW4 = (const uint4*)smc;
    const int tid  = threadIdx.x;
    const int wid  = tid >> 5;          // 0..15
    const int lane = tid & 31;
    const int g = lane >> 2, t = lane & 3;
    const int m16 = wid & 7;            // m16 tile 0..7
    const int w4  = m16 >> 1;           // 32-row group (pack layout)
    const int mt  = m16 & 1;            // m16 within group
    const int jh  = wid >> 3;           // n-half: 0 or 1
    const int cta  = blockIdx.x;
    const int tt   = cta / 3;
    const int sp   = cta % 3;
    const int spk0 = sp * 384;
    const int nch  = (sp == 2) ? 8 : 12;

    // one-time load of packed fp16 W tile
    {
        const uint4* src = &g_Wpk[(size_t)cta * 6144];
        int n4 = nch * 512;
        for (int u = tid; u < n4; u += PTHR)
            CPA16(sb + u * 16, (const char*)(src + u));
        CPC(); CPW(0);
        __syncthreads();
    }

    const size_t BTH = (size_t)Bn * Tn * Hn;
    unsigned ep = 0;

#pragma unroll 1
    for (int tstep = 0; tstep < Tn; tstep++){
        const int par = tstep & 1, np = par ^ 1;
        const int na = __ldg(&g_na[tstep]);
        const int nj = (na + 7) >> 3;
        if (nj == 0) break;
        const int ract = nj << 3;
        const __half* __restrict__ Bsrc = (tt < 32) ? g_ht[par] : g_ct[par];

        // ---- single-shot staging of ALL B chunks (threads 0..255 active) ----
        {
            int rr = tid >> 2, uu = tid & 3;
            if (rr < ract){
                const __half* rp = Bsrc + (size_t)rr * Hn + spk0;
                uint32_t dst = sb + SWB + rr * 80 + uu * 16;
#pragma unroll 1
                for (int ck = 0; ck < nch; ck++)
                    CPA16(dst + ck * BBUF, rp + ck * 32 + uu * 8);
            }
            CPC(); CPW(0);
            __syncthreads();
        }

        // ---- MMA: 16 warps, each m16 x 4 n-tiles, no internal syncs ----
        float acc[4][4];
#pragma unroll
        for (int jl = 0; jl < 4; jl++)
#pragma unroll
            for (int q = 0; q < 4; q++) acc[jl][q] = 0.f;

#pragma unroll 1
        for (int ck = 0; ck < nch; ck++){
            const uint32_t Bb = sb + SWB + ck * BBUF;
#pragma unroll
            for (int kk = 0; kk < 2; kk++){
                uint4 av = sW4[((((ck * 2 + kk) * 4 + w4) * 2 + mt) * 32) + lane];
#pragma unroll
                for (int jl = 0; jl < 4; jl++){
                    int j = jh * 4 + jl;
                    if (j < nj){
                        uint32_t bbase = Bb + (j * 8 + g) * 80 + kk * 32 + t * 4;
                        uint32_t b0 = lds32(bbase);
                        uint32_t b1 = lds32(bbase + 16);
                        MMA_F16(acc[jl], av.x, av.y, av.z, av.w, b0, b1);
                    }
                }
            }
        }

        // epilogue: partials -> g_P[(sp*64+col)][row], active tiles only
#pragma unroll
        for (int jl = 0; jl < 4; jl++){
            int j = jh * 4 + jl;
            if (j < nj){
#pragma unroll
                for (int q = 0; q < 4; q++){
                    int row = tt * 128 + m16 * 16 + g + (q >> 1) * 8;
                    int col = j * 8 + t * 2 + (q & 1);
                    g_P[((size_t)(sp * 64 + col)) * 6144 + row] = acc[jl][q];
                }
            }
        }

        gridbar(++ep);

        // fused cell phase — active batches only (sorted desc => bp < na)
        const int ncell = na << 10;
        for (int e = cta * PTHR + tid; e < ncell; e += NCTA * PTHR){
            int j  = e & (Hn - 1);
            int bp = e >> 10;
            int borig = __ldg(&g_perm[bp]);

            float si = 0.f, sf = 0.f, sg = 0.f, so = 0.f;
#pragma unroll
            for (int s2 = 0; s2 < 3; s2++){
                const float* Pp = g_P + ((size_t)(s2 * 64 + bp)) * 6144;
                si += Pp[j]        + Pp[4096 + j];
                sf += Pp[1024 + j] + Pp[5120 + j];
                sg += Pp[2048 + j];
                so += Pp[3072 + j];
            }
            size_t pxb = ((size_t)tstep * Bn + borig) * G4 + j;
            float pi = g_prex[pxb]          + si;
            float pf = g_prex[pxb + Hn]     + sf;
            float pg = g_prex[pxb + 2*Hn]   + sg;
            float po = g_prex[pxb + 3*Hn]   + so;
            float cold = g_c[par][e];

            float ig = sigf(pi);
            float fg = sigf(pf);
            float gv = tanhf(pg);
            float cn = fg * cold + ig * gv;
            float og = sigf(po + cn);
            float hn = og * tanhf(cn);

            g_c[np][e]  = cn;
            g_ht[np][e] = __float2half_rn(hn);
            g_ct[np][e] = __float2half_rn(cn);

            size_t ob = ((size_t)borig * Tn + tstep) * Hn + j;
            out[ob] = hn;
            if (writeC) out[BTH + ob] = cn;
        }

        gridbar(++ep);
    }
}

// ---------------------------------------------------------------------------
extern "C" void kernel_launch(void* const* d_in, const int* in_sizes, int n_in,
                              void* d_out, int out_size)
{
    const float* x    = (const float*)d_in[0];
    const float* h0   = (const float*)d_in[1];
    const float* c0   = (const float*)d_in[2];
    const float* wih  = (const float*)d_in[3];
    const float* whh  = (const float*)d_in[4];
    const float* wrec = (const float*)d_in[5];
    const float* bias = (const float*)d_in[6];
    const int* lengths = (const int*)d_in[7];
    float* out = (float*)d_out;
    int writeC = (out_size >= 2 * Bn * Tn * Hn) ? 1 : 0;

    cudaFuncSetAttribute(gemm_prex, cudaFuncAttributeMaxDynamicSharedMemorySize, PX_SMEM);
    cudaFuncSetAttribute(persist_kernel, cudaFuncAttributeMaxDynamicSharedMemorySize, PERS_SMEM);

    prep_sort<<<1, 256>>>(lengths);
    pack_w<<<1024, 256>>>(whh, wrec);
    pack_wih<<<512, 256>>>(wih);
    cvt_x<<<1024, 256>>>(x);
    out_zero<<<1024, 256>>>(out, (size_t)out_size / 4);
    init_state<<<256, 256>>>(h0, c0);
    gemm_prex<<<dim3(32, 188), 128, PX_SMEM>>>(bias, lengths);
    persist_kernel<<<NCTA, PTHR, PERS_SMEM>>>(out, writeC);
}

// round 16
// speedup vs baseline: 1.2093x; 1.0645x over previous
#include <cuda_runtime.h>
#include <cuda_fp16.h>
#include <cstdint>

#define Bn 64
#define Tn 188
#define In 512
#define Hn 1024
#define G4 (4*Hn)
#define NCTA 144
#define NTHR 256
#define PTHR 512

// ---------------- persistent device scratch (allocation-free rule) ----------
__device__ float  g_prex[(size_t)Tn * Bn * G4];     // [t][b_orig][gate*1024+j]
__device__ float  g_P[(size_t)3 * Bn * 6144];       // [sp*64+col(bp)][row]
__device__ float  g_c[2][Bn * Hn];                  // fp32 cell state (permuted b)
__device__ __half g_ht[2][Bn * Hn];                 // fp16 hidden (permuted b)
__device__ __half g_ct[2][Bn * Hn];                 // fp16 cell (permuted b)
__device__ uint4  g_Wpk[(size_t)NCTA * 6144];       // packed fp16 W frags per CTA
__device__ uint4  g_Wpih[(size_t)32 * 8192];        // packed fp16 Wih frags per m-tile
__device__ __half g_X[(size_t)Bn * Tn * In];        // x fp16
__device__ int    g_perm[Bn];                       // bp -> original b
__device__ int    g_na[Tn];                         // exact active count per step
__device__ unsigned g_flags[NCTA * 8];              // per-CTA epoch flags, 32B stride

__device__ __forceinline__ float sigf(float x){ return 1.f / (1.f + __expf(-x)); }

#define CPA16(dst, src) \
    asm volatile("cp.async.cg.shared.global [%0], [%1], 16;" :: "r"(dst), "l"(src) : "memory")
#define CPC()  asm volatile("cp.async.commit_group;" ::: "memory")
#define CPW(n) asm volatile("cp.async.wait_group %0;" :: "n"(n) : "memory")

#define MMA_F16(acc, a0,a1,a2,a3, b0,b1) \
    asm volatile("mma.sync.aligned.m16n8k16.row.col.f32.f16.f16.f32 " \
        "{%0,%1,%2,%3}, {%4,%5,%6,%7}, {%8,%9}, {%0,%1,%2,%3};" \
        : "+f"((acc)[0]), "+f"((acc)[1]), "+f"((acc)[2]), "+f"((acc)[3]) \
        : "r"(a0), "r"(a1), "r"(a2), "r"(a3), "r"(b0), "r"(b1))

__device__ __forceinline__ uint32_t lds32(uint32_t a){
    uint32_t v; asm volatile("ld.shared.b32 %0, [%1];" : "=r"(v) : "r"(a)); return v;
}
__device__ __forceinline__ uint32_t h2pk(float a, float b){
    __half2 h = __floats2half2_rn(a, b);
    return *(uint32_t*)&h;
}

// ---------------------------------------------------------------------------
// Prep kernels
// ---------------------------------------------------------------------------
__device__ __forceinline__ float Wat(const float* whh, const float* wrec, int r, int c){
    return (r < 4096) ? whh[(size_t)r * Hn + c] : wrec[(size_t)(r - 4096) * Hn + c];
}

// persist W pack (VALIDATED R8): slot=(((ck*2+kk)*4+w)*2+mt)*32+lane
__global__ void pack_w(const float* __restrict__ whh, const float* __restrict__ wrec){
    const int total = NCTA * 6144;
    for (int s = blockIdx.x * blockDim.x + threadIdx.x; s < total;
         s += gridDim.x * blockDim.x){
        int cta = s / 6144, idx = s % 6144;
        int tt = cta / 3, sp = cta % 3;
        int nch = (sp == 2) ? 8 : 12;
        int lane = idx & 31; int r = idx >> 5;
        int mt = r & 1; r >>= 1;
        int w  = r & 3; r >>= 2;
        int kk = r & 1; int ck = r >> 1;
        if (ck >= nch) continue;
        int g = lane >> 2, t = lane & 3;
        int R0 = tt * 128 + w * 32 + mt * 16 + g;
        int C0 = sp * 384 + ck * 32 + kk * 16 + 2 * t;
        uint4 v;
        v.x = h2pk(Wat(whh, wrec, R0,     C0),     Wat(whh, wrec, R0,     C0 + 1));
        v.y = h2pk(Wat(whh, wrec, R0 + 8, C0),     Wat(whh, wrec, R0 + 8, C0 + 1));
        v.z = h2pk(Wat(whh, wrec, R0,     C0 + 8), Wat(whh, wrec, R0,     C0 + 9));
        v.w = h2pk(Wat(whh, wrec, R0 + 8, C0 + 8), Wat(whh, wrec, R0 + 8, C0 + 9));
        g_Wpk[(size_t)cta * 6144 + idx] = v;
    }
}

// Wih pack (VALIDATED R9)
__global__ void pack_wih(const float* __restrict__ wih){
    const int total = 32 * 8192;
    for (int s = blockIdx.x * blockDim.x + threadIdx.x; s < total;
         s += gridDim.x * blockDim.x){
        int mtile = s / 8192, idx = s % 8192;
        int lane = idx & 31; int r = idx >> 5;
        int mt = r & 1; r >>= 1;
        int w  = r & 3; r >>= 2;
        int kk = r & 1; int ck = r >> 1;
        int g = lane >> 2, t = lane & 3;
        int R0 = mtile * 128 + w * 32 + mt * 16 + g;
        int C0 = ck * 32 + kk * 16 + 2 * t;
        const float* p0 = wih + (size_t)R0 * In;
        const float* p1 = wih + (size_t)(R0 + 8) * In;
        uint4 v;
        v.x = h2pk(p0[C0],     p0[C0 + 1]);
        v.y = h2pk(p1[C0],     p1[C0 + 1]);
        v.z = h2pk(p0[C0 + 8], p0[C0 + 9]);
        v.w = h2pk(p1[C0 + 8], p1[C0 + 9]);
        g_Wpih[s] = v;
    }
}

__global__ void cvt_x(const float* __restrict__ x){
    const size_t n3 = (size_t)Bn * Tn * In;
    for (size_t i = (size_t)blockIdx.x * blockDim.x + threadIdx.x; i < n3;
         i += (size_t)gridDim.x * blockDim.x)
        g_X[i] = __float2half_rn(x[i]);
}

__global__ void out_zero(float* __restrict__ out, size_t n4){
    float4 z = make_float4(0.f, 0.f, 0.f, 0.f);
    for (size_t i = (size_t)blockIdx.x * blockDim.x + threadIdx.x; i < n4;
         i += (size_t)gridDim.x * blockDim.x)
        ((float4*)out)[i] = z;
}

// rank-sort lengths descending (stable), per-step active counts
__global__ void prep_sort(const int* __restrict__ lengths){
    __shared__ int sl[Bn];
    int tid = threadIdx.x;
    if (tid < Bn) sl[tid] = lengths[tid];
    __syncthreads();
    if (tid < Bn){
        int L = sl[tid]; int r = 0;
#pragma unroll
        for (int k = 0; k < Bn; k++)
            r += (sl[k] > L) || (sl[k] == L && k < tid);
        g_perm[r] = tid;
    }
    if (tid < Tn){
        int c = 0;
#pragma unroll
        for (int k = 0; k < Bn; k++) c += (sl[k] > tid);
        g_na[tid] = c;
    }
}

__global__ void init_state(const float* __restrict__ h0, const float* __restrict__ c0){
    int i = blockIdx.x * blockDim.x + threadIdx.x;
    if (i < NCTA * 8) g_flags[i] = 0;               // reset barrier flags each replay
    if (i < Bn * Hn){
        int bp = i >> 10, j = i & (Hn - 1);
        int b = g_perm[bp];
        float h = h0[(size_t)b * Hn + j], c = c0[(size_t)b * Hn + j];
        g_c[0][i]  = c;
        g_ht[0][i] = __float2half_rn(h);
        g_ct[0][i] = __float2half_rn(c);
    }
}

// ---------------------------------------------------------------------------
// fp16 input-projection GEMM (VALIDATED R9/R10) + dead-tile skip
// ---------------------------------------------------------------------------
#define PXB 5120
#define PX_SMEM (2 * PXB)

__global__ void __launch_bounds__(128)
gemm_prex(const float* __restrict__ bias, const int* __restrict__ lengths)
{
    const int nb = blockIdx.y;
    {
        int n0 = nb * 64;
        int b0 = n0 / Tn, t0 = n0 - b0 * Tn;
        bool cross = ((n0 + 63) / Tn) != b0;
        if (!cross && t0 >= __ldg(&lengths[b0])) return;
    }

    extern __shared__ __align__(16) char smc[];
    const uint32_t sb = (uint32_t)__cvta_generic_to_shared(smc);
    const int tid = threadIdx.x;
    const int wid = tid >> 5;
    const int lane = tid & 31;
    const int g = lane >> 2, t = lane & 3;
    const int m = blockIdx.x;

    const uint4* __restrict__ Ap = g_Wpih + (size_t)m * 8192;
    const __half* __restrict__ B = g_X + (size_t)nb * 64 * In;

    float acc[2][8][4];
#pragma unroll
    for (int mt = 0; mt < 2; mt++)
#pragma unroll
        for (int j = 0; j < 8; j++)
#pragma unroll
            for (int q = 0; q < 4; q++) acc[mt][j][q] = 0.f;

#define PX_ST(buf, ck) do {                                                    \
        for (int u = tid; u < 256; u += 128){                                  \
            int rr = u >> 2, uu = u & 3;                                       \
            CPA16(sb + (buf) * PXB + rr * 80 + uu * 16,                        \
                  B + (size_t)rr * In + (ck) * 32 + uu * 8);                   \
        }                                                                      \
    } while (0)

#define PX_LDA(dst, ck) do {                                                   \
        (dst)[0][0] = Ap[((((ck) * 2 + 0) * 4 + wid) * 2 + 0) * 32 + lane];    \
        (dst)[0][1] = Ap[((((ck) * 2 + 0) * 4 + wid) * 2 + 1) * 32 + lane];    \
        (dst)[1][0] = Ap[((((ck) * 2 + 1) * 4 + wid) * 2 + 0) * 32 + lane];    \
        (dst)[1][1] = Ap[((((ck) * 2 + 1) * 4 + wid) * 2 + 1) * 32 + lane];    \
    } while (0)

    PX_ST(0, 0); CPC();
    uint4 av[2][2];
    PX_LDA(av, 0);

#pragma unroll 1
    for (int ch = 0; ch < 16; ch++){
        CPW(0);
        __syncthreads();
        if (ch + 1 < 16){ PX_ST((ch + 1) & 1, ch + 1); CPC(); }
        uint4 nx[2][2];
        if (ch + 1 < 16) PX_LDA(nx, ch + 1);

        const uint32_t Bb = sb + (ch & 1) * PXB;
#pragma unroll
        for (int kk = 0; kk < 2; kk++){
            uint32_t b[8][2];
#pragma unroll
            for (int j = 0; j < 8; j++){
                uint32_t bbase = Bb + (j * 8 + g) * 80 + kk * 32 + t * 4;
                b[j][0] = lds32(bbase);
                b[j][1] = lds32(bbase + 16);
            }
#pragma unroll
            for (int mt = 0; mt < 2; mt++){
                uint4 a = av[kk][mt];
#pragma unroll
                for (int j = 0; j < 8; j++)
                    MMA_F16(acc[mt][j], a.x, a.y, a.z, a.w, b[j][0], b[j][1]);
            }
        }
        if (ch + 1 < 16){
            av[0][0] = nx[0][0]; av[0][1] = nx[0][1];
            av[1][0] = nx[1][0]; av[1][1] = nx[1][1];
        }
    }

#pragma unroll
    for (int mt = 0; mt < 2; mt++){
        int rowb = m * 128 + wid * 32 + mt * 16;
        float bs0 = bias[rowb + g];
        float bs1 = bias[rowb + g + 8];
#pragma unroll
        for (int j = 0; j < 8; j++)
#pragma unroll
            for (int q = 0; q < 4; q++){
                int row = rowb + g + (q >> 1) * 8;
                int n   = blockIdx.y * 64 + j * 8 + t * 2 + (q & 1);
                int bq  = n / Tn, tq = n - bq * Tn;
                g_prex[((size_t)tq * Bn + bq) * G4 + row] =
                    acc[mt][j][q] + ((q >> 1) ? bs1 : bs0);
            }
    }
}

// ---------------------------------------------------------------------------
// Persistent recurrent kernel: 16 warps + release/acquire barrier + cell prefetch
// ---------------------------------------------------------------------------
#define SWB  98304
#define BBUF 5120
#define PERS_SMEM (SWB + 12 * BBUF)     // 96KB W + 60KB B = 156KB

// Release/acquire flag barrier: arrival = st.release (orders prior writes),
// release = 144 parallel acquire-spins; transitivity via bar.sync.
__device__ __forceinline__ void gridbar(unsigned ep){
    __syncthreads();
    if (threadIdx.x == 0){
        asm volatile("st.release.gpu.global.u32 [%0], %1;"
                     :: "l"(&g_flags[blockIdx.x * 8]), "r"(ep) : "memory");
    }
    if (threadIdx.x < NCTA){
        unsigned v;
        do {
            asm volatile("ld.acquire.gpu.global.u32 %0, [%1];"
                         : "=r"(v) : "l"(&g_flags[threadIdx.x * 8]) : "memory");
        } while (v < ep);
    }
    __syncthreads();
}

__global__ void __launch_bounds__(PTHR, 1)
persist_kernel(float* __restrict__ out, int writeC)
{
    extern __shared__ __align__(16) char smc[];
    const uint32_t sb = (uint32_t)__cvta_generic_to_shared(smc);
    const uint4* sW4 = (const uint4*)smc;
    const int tid  = threadIdx.x;
    const int wid  = tid >> 5;          // 0..15
    const int lane = tid & 31;
    const int g = lane >> 2, t = lane & 3;
    const int m16 = wid & 7;
    const int w4  = m16 >> 1;
    const int mt  = m16 & 1;
    const int jh  = wid >> 3;
    const int cta  = blockIdx.x;
    const int tt   = cta / 3;
    const int sp   = cta % 3;
    const int spk0 = sp * 384;
    const int nch  = (sp == 2) ? 8 : 12;

    // one-time load of packed fp16 W tile
    {
        const uint4* src = &g_Wpk[(size_t)cta * 6144];
        int n4 = nch * 512;
        for (int u = tid; u < n4; u += PTHR)
            CPA16(sb + u * 16, (const char*)(src + u));
        CPC(); CPW(0);
        __syncthreads();
    }

    const size_t BTH = (size_t)Bn * Tn * Hn;
    unsigned ep = 0;

    // fixed cell element for this thread (73728 threads >= 65536 elements)
    const int ce = cta * PTHR + tid;
    const int cj  = ce & (Hn - 1);
    const int cbp = ce >> 10;
    const int cborig = (ce < Bn * Hn) ? __ldg(&g_perm[cbp]) : 0;

#pragma unroll 1
    for (int tstep = 0; tstep < Tn; tstep++){
        const int par = tstep & 1, np = par ^ 1;
        const int na = __ldg(&g_na[tstep]);
        const int nj = (na + 7) >> 3;
        if (nj == 0) break;
        const int ract = nj << 3;
        const __half* __restrict__ Bsrc = (tt < 32) ? g_ht[par] : g_ct[par];

        // ---- single-shot staging of ALL B chunks (threads 0..255 active) ----
        {
            int rr = tid >> 2, uu = tid & 3;
            if (rr < ract){
                const __half* rp = Bsrc + (size_t)rr * Hn + spk0;
                uint32_t dst = sb + SWB + rr * 80 + uu * 16;
#pragma unroll 1
                for (int ck = 0; ck < nch; ck++)
                    CPA16(dst + ck * BBUF, rp + ck * 32 + uu * 8);
            }
            CPC(); CPW(0);
            __syncthreads();
        }

        // ---- MMA: 16 warps, each m16 x 4 n-tiles, no internal syncs ----
        float acc[4][4];
#pragma unroll
        for (int jl = 0; jl < 4; jl++)
#pragma unroll
            for (int q = 0; q < 4; q++) acc[jl][q] = 0.f;

#pragma unroll 1
        for (int ck = 0; ck < nch; ck++){
            const uint32_t Bb = sb + SWB + ck * BBUF;
#pragma unroll
            for (int kk = 0; kk < 2; kk++){
                uint4 av = sW4[((((ck * 2 + kk) * 4 + w4) * 2 + mt) * 32) + lane];
#pragma unroll
                for (int jl = 0; jl < 4; jl++){
                    int j = jh * 4 + jl;
                    if (j < nj){
                        uint32_t bbase = Bb + (j * 8 + g) * 80 + kk * 32 + t * 4;
                        uint32_t b0 = lds32(bbase);
                        uint32_t b1 = lds32(bbase + 16);
                        MMA_F16(acc[jl], av.x, av.y, av.z, av.w, b0, b1);
                    }
                }
            }
        }

        // epilogue: partials -> g_P[(sp*64+col)][row], active tiles only
#pragma unroll
        for (int jl = 0; jl < 4; jl++){
            int j = jh * 4 + jl;
            if (j < nj){
#pragma unroll
                for (int q = 0; q < 4; q++){
                    int row = tt * 128 + m16 * 16 + g + (q >> 1) * 8;
                    int col = j * 8 + t * 2 + (q & 1);
                    g_P[((size_t)(sp * 64 + col)) * 6144 + row] = acc[jl][q];
                }
            }
        }

        // ---- prefetch cell inputs (independent of this step's GEMM/P) ----
        const bool cellv = ce < (na << 10);
        float pxi = 0.f, pxf = 0.f, pxg = 0.f, pxo = 0.f, cold = 0.f;
        if (cellv){
            const float* px = g_prex + ((size_t)tstep * Bn + cborig) * G4 + cj;
            pxi = px[0];
            pxf = px[Hn];
            pxg = px[2 * Hn];
            pxo = px[3 * Hn];
            cold = g_c[par][ce];
        }

        gridbar(++ep);

        // fused cell phase — one element per thread
        if (cellv){
            float si = 0.f, sf = 0.f, sg = 0.f, so = 0.f;
#pragma unroll
            for (int s2 = 0; s2 < 3; s2++){
                const float* Pp = g_P + ((size_t)(s2 * 64 + cbp)) * 6144;
                si += Pp[cj]        + Pp[4096 + cj];
                sf += Pp[1024 + cj] + Pp[5120 + cj];
                sg += Pp[2048 + cj];
                so += Pp[3072 + cj];
            }
            float pi = pxi + si;
            float pf = pxf + sf;
            float pg = pxg + sg;
            float po = pxo + so;

            float ig = sigf(pi);
            float fg = sigf(pf);
            float gv = tanhf(pg);
            float cn = fg * cold + ig * gv;
            float og = sigf(po + cn);
            float hn = og * tanhf(cn);

            g_c[np][ce]  = cn;
            g_ht[np][ce] = __float2half_rn(hn);
            g_ct[np][ce] = __float2half_rn(cn);

            size_t ob = ((size_t)cborig * Tn + tstep) * Hn + cj;
            out[ob] = hn;
            if (writeC) out[BTH + ob] = cn;
        }

        gridbar(++ep);
    }
}

// ---------------------------------------------------------------------------
extern "C" void kernel_launch(void* const* d_in, const int* in_sizes, int n_in,
                              void* d_out, int out_size)
{
    const float* x    = (const float*)d_in[0];
    const float* h0   = (const float*)d_in[1];
    const float* c0   = (const float*)d_in[2];
    const float* wih  = (const float*)d_in[3];
    const float* whh  = (const float*)d_in[4];
    const float* wrec = (const float*)d_in[5];
    const float* bias = (const float*)d_in[6];
    const int* lengths = (const int*)d_in[7];
    float* out = (float*)d_out;
    int writeC = (out_size >= 2 * Bn * Tn * Hn) ? 1 : 0;

    cudaFuncSetAttribute(gemm_prex, cudaFuncAttributeMaxDynamicSharedMemorySize, PX_SMEM);
    cudaFuncSetAttribute(persist_kernel, cudaFuncAttributeMaxDynamicSharedMemorySize, PERS_SMEM);

    prep_sort<<<1, 256>>>(lengths);
    pack_w<<<1024, 256>>>(whh, wrec);
    pack_wih<<<512, 256>>>(wih);
    cvt_x<<<1024, 256>>>(x);
    out_zero<<<1024, 256>>>(out, (size_t)out_size / 4);
    init_state<<<256, 256>>>(h0, c0);
    gemm_prex<<<dim3(32, 188), 128, PX_SMEM>>>(bias, lengths);
    persist_kernel<<<NCTA, PTHR, PERS_SMEM>>>(out, writeC);
}